// round 12
// baseline (speedup 1.0000x reference)
#include <cuda_runtime.h>
#include <cstddef>

// PCEN transform:
//   m_t = (1-S)*m_{t-1} + S*x_t   (EMA over time axis, per [b,f] row)
//   out = (x / (m+EPS)^ALPHA + DELTA)^R - DELTA^R,  R = 0.5
//
// R11: one warp per row; each lane owns 8 contiguous elements (2x float4,
// back-to-back loads -> MLP_p1=2). Affine warp scan over 32 lane-segments.
// Exclusive prefix derived arithmetically: excl = (v - b) / c^8 (no SHFL).
// Recurrence on q-scale (q_t = c*q_{t-1} + x_t, m = S*q) -> pure FMA chains.

#define S_CONST     0.025f
#define C_CONST     0.975f
#define EPS_CONST   1e-6f
#define ALPHA_CONST 0.98f
#define DELTA_CONST 2.0f
#define SQRT_DELTA  1.41421356237309515f   // sqrt(2)

#define T_LEN   4096
#define CHUNK   256          // elements per warp-chunk (32 lanes x 8)
#define NCHUNK  (T_LEN / CHUNK)   // 16
#define WARPS_PER_BLOCK 8
#define BLOCK_THREADS   (WARPS_PER_BLOCK * 32)

__device__ __forceinline__ float ex2_approx(float a) {
    float r; asm("ex2.approx.f32 %0, %1;" : "=f"(r) : "f"(a)); return r;
}
__device__ __forceinline__ float lg2_approx(float a) {
    float r; asm("lg2.approx.f32 %0, %1;" : "=f"(r) : "f"(a)); return r;
}
__device__ __forceinline__ float sqrt_approx(float a) {
    float r; asm("sqrt.approx.f32 %0, %1;" : "=f"(r) : "f"(a)); return r;
}

// fused epilogue on q-scale: m = S*q
//   (x * (S*q + EPS)^-ALPHA + DELTA)^0.5 - DELTA^0.5
__device__ __forceinline__ float pcen_epilogue(float xv, float q) {
    float p = ex2_approx(-ALPHA_CONST * lg2_approx(fmaf(S_CONST, q, EPS_CONST)));
    return sqrt_approx(fmaf(xv, p, DELTA_CONST)) - SQRT_DELTA;
}

__global__ __launch_bounds__(BLOCK_THREADS, 7)
void pcen_kernel(const float* __restrict__ x, float* __restrict__ out, int nrows)
{
    const int gwarp = (blockIdx.x * BLOCK_THREADS + threadIdx.x) >> 5;
    const int lane  = threadIdx.x & 31;
    if (gwarp >= nrows) return;

    // lane's 8-element segment base within each chunk
    const float* xr  = x   + (size_t)gwarp * T_LEN + lane * 8;
    float*       orw = out + (size_t)gwarp * T_LEN + lane * 8;

    // Decay powers (all compile-time constants except clane)
    const float c2   = C_CONST * C_CONST;
    const float c4   = c2 * c2;
    const float f1   = c4 * c4;     // c^8   (per-lane segment factor)
    const float f2   = f1 * f1;     // c^16
    const float f3   = f2 * f2;     // c^32
    const float f4   = f3 * f3;     // c^64
    const float f5   = f4 * f4;     // c^128
    const float cchk = f5 * f5;     // c^256 (per-chunk carry factor)
    const float inv_f1 = 1.0f / f1; // c^-8  (compile-time)
    // c^(8*lane) via MUFU (once per thread)
    const float clane = ex2_approx(8.0f * (float)lane * lg2_approx(C_CONST));

    float carry = 0.0f;   // q-scale carry entering this chunk

    // Prefetch chunk 0 (two back-to-back 16B loads -> 2 in flight)
    float4 xa = reinterpret_cast<const float4*>(xr)[0];
    float4 xb = reinterpret_cast<const float4*>(xr)[1];

    #pragma unroll 1
    for (int ch = 0; ch < NCHUNK; ++ch) {
        // Prefetch next chunk while we scan the current one
        float4 na = xa, nb = xb;
        if (ch + 1 < NCHUNK) {
            const float* nxt = xr + (ch + 1) * CHUNK;
            na = reinterpret_cast<const float4*>(nxt)[0];
            nb = reinterpret_cast<const float4*>(nxt)[1];
        }

        // ---- local q-recurrence over this lane's 8 elements (zero-init) ----
        float b = xa.x;
        b = fmaf(C_CONST, b, xa.y);
        b = fmaf(C_CONST, b, xa.z);
        b = fmaf(C_CONST, b, xa.w);
        b = fmaf(C_CONST, b, xb.x);
        b = fmaf(C_CONST, b, xb.y);
        b = fmaf(C_CONST, b, xb.z);
        b = fmaf(C_CONST, b, xb.w);

        // ---- inclusive affine warp scan: v_l = b_l + c^8 * v_{l-1} ----
        float v = b, u;
        u = __shfl_up_sync(0xffffffffu, v, 1);  if (lane >= 1)  v = fmaf(f1, u, v);
        u = __shfl_up_sync(0xffffffffu, v, 2);  if (lane >= 2)  v = fmaf(f2, u, v);
        u = __shfl_up_sync(0xffffffffu, v, 4);  if (lane >= 4)  v = fmaf(f3, u, v);
        u = __shfl_up_sync(0xffffffffu, v, 8);  if (lane >= 8)  v = fmaf(f4, u, v);
        u = __shfl_up_sync(0xffffffffu, v, 16); if (lane >= 16) v = fmaf(f5, u, v);

        // exclusive prefix, arithmetically: excl = (v - b) * c^-8
        // (lane 0: v == b exactly -> excl == 0; no SHFL, no predicate)
        float excl = (v - b) * inv_f1;

        // fold cross-chunk carry: true q entering this lane's segment
        float q = fmaf(clane, carry, excl);

        // carry for next chunk (broadcast lane 31's inclusive value)
        float v31 = __shfl_sync(0xffffffffu, v, 31);
        carry = fmaf(cchk, carry, v31);

        // ---- reconstruct q per element + fused PCEN epilogue ----
        float4 oa, ob;
        q = fmaf(C_CONST, q, xa.x);  oa.x = pcen_epilogue(xa.x, q);
        q = fmaf(C_CONST, q, xa.y);  oa.y = pcen_epilogue(xa.y, q);
        q = fmaf(C_CONST, q, xa.z);  oa.z = pcen_epilogue(xa.z, q);
        q = fmaf(C_CONST, q, xa.w);  oa.w = pcen_epilogue(xa.w, q);
        q = fmaf(C_CONST, q, xb.x);  ob.x = pcen_epilogue(xb.x, q);
        q = fmaf(C_CONST, q, xb.y);  ob.y = pcen_epilogue(xb.y, q);
        q = fmaf(C_CONST, q, xb.z);  ob.z = pcen_epilogue(xb.z, q);
        q = fmaf(C_CONST, q, xb.w);  ob.w = pcen_epilogue(xb.w, q);

        float* od = orw + ch * CHUNK;
        reinterpret_cast<float4*>(od)[0] = oa;
        reinterpret_cast<float4*>(od)[1] = ob;

        xa = na;  xb = nb;
    }
}

extern "C" void kernel_launch(void* const* d_in, const int* in_sizes, int n_in,
                              void* d_out, int out_size)
{
    const float* x = (const float*)d_in[0];
    float* out = (float*)d_out;

    int nrows = in_sizes[0] / T_LEN;                    // 32*256 = 8192
    int blocks = (nrows + WARPS_PER_BLOCK - 1) / WARPS_PER_BLOCK;  // 1024

    pcen_kernel<<<blocks, BLOCK_THREADS>>>(x, out, nrows);
}